// round 3
// baseline (speedup 1.0000x reference)
#include <cuda_runtime.h>

#define BATCH  32768
#define NCONT  56
#define NB     16
#define NCAT   8
#define NUNIQ  100
#define NCOMP  8
#define SEPF   1e-3f
#define T1F    10.0f

// Scratch for categorical indices (allocation-free rule: __device__ global).
__device__ int g_codes[BATCH * NCAT];

// Stable softplus: max(x,0) + log1p(exp(-|x|)); 2 MUFU ops via fast intrinsics.
__device__ __forceinline__ float sp(float x) {
    float e = __expf(-fabsf(x));
    return fmaxf(x, 0.0f) + __logf(1.0f + e);
}

// ---------------------------------------------------------------------------
// Kernel 1: extract one-hot indices from B_cat (fully coalesced float4 scan).
// Exactly one element per (row, cat) block of 100 is 1.0, so every code slot
// is written exactly once per launch -> deterministic.
// ---------------------------------------------------------------------------
__global__ void k_codes(const float* __restrict__ bcat, int total4) {
    int idx = blockIdx.x * blockDim.x + threadIdx.x;
    if (idx >= total4) return;
    float4 v = reinterpret_cast<const float4*>(bcat)[idx];
    if (v.x > 0.5f || v.y > 0.5f || v.z > 0.5f || v.w > 0.5f) {
        float vals[4] = {v.x, v.y, v.z, v.w};
        int e = idx * 4;
        #pragma unroll
        for (int j = 0; j < 4; j++) {
            if (vals[j] > 0.5f) {
                int ee  = e + j;
                int b   = ee / (NCAT * NUNIQ);
                int rem = ee - b * (NCAT * NUNIQ);
                g_codes[b * NCAT + rem / NUNIQ] = rem % NUNIQ;
            }
        }
    }
}

// ---------------------------------------------------------------------------
// Kernel 2: main fused compute, one thread per batch row.
//   - cont weights read via uniform __ldg (one broadcast load per warp,
//     L1-resident 61 KB working set) -- no shared memory, no attribute opt-in
//   - B row streamed via per-thread float4 __ldg with 1-feature prefetch
//   - cat contribution via L1-resident gathers using g_codes
//   - softplus + feature-sum + cumsum epilogue, float2 stores
// ---------------------------------------------------------------------------
__global__ void __launch_bounds__(128) k_main(
    const float* __restrict__ B,
    const float* __restrict__ Wh,  const float* __restrict__ bh,
    const float* __restrict__ Wv,  const float* __restrict__ bv,
    const float* __restrict__ Wic, const float* __restrict__ bic,
    const float* __restrict__ Whc, const float* __restrict__ Wvc,
    const float* __restrict__ Wicc,
    float* __restrict__ out)
{
    const int row = blockIdx.x * blockDim.x + threadIdx.x;
    if (row >= BATCH) return;

    float hs[NCOMP], vs[NCOMP];
    #pragma unroll
    for (int c = 0; c < NCOMP; c++) { hs[c] = 0.0f; vs[c] = 0.0f; }
    float ic = 0.0f;

    const float4* brow = reinterpret_cast<const float4*>(B) + (size_t)row * (NCONT * NB / 4);

    // Prefetch first feature's 16 B-values (4 x float4)
    float4 pb0 = __ldg(brow + 0), pb1 = __ldg(brow + 1),
           pb2 = __ldg(brow + 2), pb3 = __ldg(brow + 3);

    for (int i = 0; i < NCONT; i++) {
        float bvals[NB];
        bvals[0]=pb0.x;  bvals[1]=pb0.y;  bvals[2]=pb0.z;  bvals[3]=pb0.w;
        bvals[4]=pb1.x;  bvals[5]=pb1.y;  bvals[6]=pb1.z;  bvals[7]=pb1.w;
        bvals[8]=pb2.x;  bvals[9]=pb2.y;  bvals[10]=pb2.z; bvals[11]=pb2.w;
        bvals[12]=pb3.x; bvals[13]=pb3.y; bvals[14]=pb3.z; bvals[15]=pb3.w;
        if (i + 1 < NCONT) {                       // prefetch next feature
            const float4* nx = brow + (i + 1) * 4;
            pb0 = __ldg(nx + 0); pb1 = __ldg(nx + 1);
            pb2 = __ldg(nx + 2); pb3 = __ldg(nx + 3);
        }

        float h[NCOMP], v[NCOMP];
        #pragma unroll
        for (int c = 0; c < NCOMP; c++) { h[c] = 0.0f; v[c] = 0.0f; }

        #pragma unroll
        for (int k = 0; k < NB; k++) {
            const int wi = (k * NCONT + i) * NCOMP;   // uniform across warp
            const float4* whp = reinterpret_cast<const float4*>(Wh + wi);
            const float4* wvp = reinterpret_cast<const float4*>(Wv + wi);
            float4 wh0 = __ldg(whp + 0), wh1 = __ldg(whp + 1);
            float4 wv0 = __ldg(wvp + 0), wv1 = __ldg(wvp + 1);
            float wic  = __ldg(Wic + k * NCONT + i);
            float bk = bvals[k];
            h[0] = fmaf(bk, wh0.x, h[0]); h[1] = fmaf(bk, wh0.y, h[1]);
            h[2] = fmaf(bk, wh0.z, h[2]); h[3] = fmaf(bk, wh0.w, h[3]);
            h[4] = fmaf(bk, wh1.x, h[4]); h[5] = fmaf(bk, wh1.y, h[5]);
            h[6] = fmaf(bk, wh1.z, h[6]); h[7] = fmaf(bk, wh1.w, h[7]);
            v[0] = fmaf(bk, wv0.x, v[0]); v[1] = fmaf(bk, wv0.y, v[1]);
            v[2] = fmaf(bk, wv0.z, v[2]); v[3] = fmaf(bk, wv0.w, v[3]);
            v[4] = fmaf(bk, wv1.x, v[4]); v[5] = fmaf(bk, wv1.y, v[5]);
            v[6] = fmaf(bk, wv1.z, v[6]); v[7] = fmaf(bk, wv1.w, v[7]);
            ic   = fmaf(bk, wic, ic);
        }
        #pragma unroll
        for (int c = 0; c < NCOMP; c++) { hs[c] += sp(h[c]); vs[c] += sp(v[c]); }
    }

    // Categorical contribution: gather W_cat rows by extracted codes.
    const int4* cp = reinterpret_cast<const int4*>(g_codes + row * NCAT);
    int4 ca = cp[0], cb = cp[1];
    int cd[NCAT] = {ca.x, ca.y, ca.z, ca.w, cb.x, cb.y, cb.z, cb.w};
    #pragma unroll
    for (int f = 0; f < NCAT; f++) {
        int n = cd[f];
        const float4* wh = reinterpret_cast<const float4*>(Whc + (f * NUNIQ + n) * NCOMP);
        const float4* wv = reinterpret_cast<const float4*>(Wvc + (f * NUNIQ + n) * NCOMP);
        float4 a0 = __ldg(wh + 0), a1 = __ldg(wh + 1);
        float4 b0 = __ldg(wv + 0), b1 = __ldg(wv + 1);
        hs[0] += sp(a0.x); hs[1] += sp(a0.y); hs[2] += sp(a0.z); hs[3] += sp(a0.w);
        hs[4] += sp(a1.x); hs[5] += sp(a1.y); hs[6] += sp(a1.z); hs[7] += sp(a1.w);
        vs[0] += sp(b0.x); vs[1] += sp(b0.y); vs[2] += sp(b0.z); vs[3] += sp(b0.w);
        vs[4] += sp(b1.x); vs[5] += sp(b1.y); vs[6] += sp(b1.z); vs[7] += sp(b1.w);
        ic += __ldg(Wicc + f * NUNIQ + n);
    }

    // Bias column (column N_FEATURES): softplus'ed for H/V, raw for IC.
    #pragma unroll
    for (int c = 0; c < NCOMP; c++) {
        hs[c] += sp(__ldg(bh + c));
        vs[c] += sp(__ldg(bv + c));
    }
    ic += __ldg(bic);

    // Epilogue: prefix sums, sep offsets, sign-alternating x, clamp last t.
    float2 o[NCOMP + 1];
    o[0] = make_float2(0.0f, ic);
    float cum = 0.0f, xc = ic;
    #pragma unroll
    for (int c = 0; c < NCOMP; c++) {
        cum += hs[c];
        xc  += (c & 1) ? -vs[c] : vs[c];
        o[c + 1] = make_float2(cum + SEPF * (float)(c + 1), xc);
    }
    o[NCOMP].x = fmaxf(o[NCOMP - 1].x + SEPF, T1F);

    float2* op = reinterpret_cast<float2*>(out + (size_t)row * 2 * (NCOMP + 1));
    #pragma unroll
    for (int j = 0; j < NCOMP + 1; j++) op[j] = o[j];
}

// ---------------------------------------------------------------------------
// Launch wrapper. Graph-capturable: two plain kernel launches, nothing else.
// ---------------------------------------------------------------------------
extern "C" void kernel_launch(void* const* d_in, const int* in_sizes, int n_in,
                              void* d_out, int out_size)
{
    const float* B    = (const float*)d_in[0];
    const float* Bcat = (const float*)d_in[1];
    const float* Wh   = (const float*)d_in[2];
    const float* Whc  = (const float*)d_in[3];
    const float* bh   = (const float*)d_in[4];
    const float* Wv   = (const float*)d_in[5];
    const float* Wvc  = (const float*)d_in[6];
    const float* bv   = (const float*)d_in[7];
    const float* Wic  = (const float*)d_in[8];
    const float* Wicc = (const float*)d_in[9];
    const float* bic  = (const float*)d_in[10];
    float* out = (float*)d_out;

    const int total4 = BATCH * NCAT * NUNIQ / 4;
    k_codes<<<(total4 + 255) / 256, 256>>>(Bcat, total4);

    k_main<<<BATCH / 128, 128>>>(B, Wh, bh, Wv, bv, Wic, bic,
                                 Whc, Wvc, Wicc, out);
}

// round 4
// speedup vs baseline: 1.2310x; 1.2310x over previous
#include <cuda_runtime.h>

#define BATCH  32768
#define NCONT  56
#define NB     16
#define NCAT   8
#define NUNIQ  100
#define NCOMP  8
#define TPR    4            // threads per row
#define FPT    (NCONT/TPR)  // 14 cont features per thread
#define CPT    (NCAT/TPR)   // 2 cat features per thread
#define WPITCH 20           // 8 h + 8 v + 1 ic, padded to 20 floats (16B-aligned)
#define SEPF   1e-3f
#define T1F    10.0f
#define TPB    256

// Stable softplus: max(x,0) + log1p(exp(-|x|)); fast intrinsics (err << 1e-3 budget).
__device__ __forceinline__ float sp(float x) {
    float e = __expf(-fabsf(x));
    return fmaxf(x, 0.0f) + __logf(1.0f + e);
}

// ---------------------------------------------------------------------------
// Single fused kernel. 4 threads cooperate per batch row (feature-split),
// weights staged in shared memory (conflict-free broadcast), one-hot scan
// fused, shfl reduction + epilogue on the leader lane of each 4-lane group.
// ---------------------------------------------------------------------------
extern __shared__ float sW[];   // [NB*NCONT][WPITCH]

__global__ void __launch_bounds__(TPB, 3) k_fused(
    const float* __restrict__ B,
    const float* __restrict__ Bcat,
    const float* __restrict__ Wh,  const float* __restrict__ bh,
    const float* __restrict__ Wv,  const float* __restrict__ bv,
    const float* __restrict__ Wic, const float* __restrict__ bic,
    const float* __restrict__ Whc, const float* __restrict__ Wvc,
    const float* __restrict__ Wicc,
    float* __restrict__ out)
{
    const int tid = threadIdx.x;

    // Stage cont weights: sW[(k*NCONT+i)*WPITCH + {0..7:h, 8..15:v, 16:ic}]
    for (int idx = tid; idx < NB * NCONT; idx += TPB) {
        float* dst = &sW[idx * WPITCH];
        float4 h0 = __ldg(reinterpret_cast<const float4*>(Wh + idx * NCOMP));
        float4 h1 = __ldg(reinterpret_cast<const float4*>(Wh + idx * NCOMP) + 1);
        float4 v0 = __ldg(reinterpret_cast<const float4*>(Wv + idx * NCOMP));
        float4 v1 = __ldg(reinterpret_cast<const float4*>(Wv + idx * NCOMP) + 1);
        *reinterpret_cast<float4*>(dst + 0)  = h0;
        *reinterpret_cast<float4*>(dst + 4)  = h1;
        *reinterpret_cast<float4*>(dst + 8)  = v0;
        *reinterpret_cast<float4*>(dst + 12) = v1;
        dst[16] = __ldg(Wic + idx);
    }
    __syncthreads();

    const int gt  = blockIdx.x * TPB + tid;
    const int row = gt / TPR;          // batch row
    const int fg  = gt % TPR;          // feature group 0..3

    float hs[NCOMP], vs[NCOMP];
    #pragma unroll
    for (int c = 0; c < NCOMP; c++) { hs[c] = 0.0f; vs[c] = 0.0f; }
    float ic = 0.0f;

    // ---- categorical part: scan my 2 one-hot segments of 100, gather weights
    {
        const float4* bc4 = reinterpret_cast<const float4*>(Bcat) +
                            (size_t)row * (NCAT * NUNIQ / 4);
        #pragma unroll
        for (int cf = 0; cf < CPT; cf++) {
            const int f = fg * CPT + cf;                 // cat feature index
            const int base4 = f * (NUNIQ / 4);           // 25 float4 per segment
            int code = 0;
            #pragma unroll 5
            for (int j = 0; j < NUNIQ / 4; j++) {
                float4 v = __ldg(bc4 + base4 + j);
                if (v.x > 0.5f) code = j * 4 + 0;
                if (v.y > 0.5f) code = j * 4 + 1;
                if (v.z > 0.5f) code = j * 4 + 2;
                if (v.w > 0.5f) code = j * 4 + 3;
            }
            const int wrow = (f * NUNIQ + code) * NCOMP;
            float4 a0 = __ldg(reinterpret_cast<const float4*>(Whc + wrow));
            float4 a1 = __ldg(reinterpret_cast<const float4*>(Whc + wrow) + 1);
            float4 b0 = __ldg(reinterpret_cast<const float4*>(Wvc + wrow));
            float4 b1 = __ldg(reinterpret_cast<const float4*>(Wvc + wrow) + 1);
            hs[0] += sp(a0.x); hs[1] += sp(a0.y); hs[2] += sp(a0.z); hs[3] += sp(a0.w);
            hs[4] += sp(a1.x); hs[5] += sp(a1.y); hs[6] += sp(a1.z); hs[7] += sp(a1.w);
            vs[0] += sp(b0.x); vs[1] += sp(b0.y); vs[2] += sp(b0.z); vs[3] += sp(b0.w);
            vs[4] += sp(b1.x); vs[5] += sp(b1.y); vs[6] += sp(b1.z); vs[7] += sp(b1.w);
            ic += __ldg(Wicc + f * NUNIQ + code);
        }
    }

    // ---- continuous part: my 14 features, 16-basis dot per (comp, feature)
    {
        const float4* brow = reinterpret_cast<const float4*>(B) +
                             (size_t)row * (NCONT * NB / 4);
        const int i0 = fg * FPT;

        // prefetch first feature's basis values
        const float4* bp = brow + i0 * 4;
        float4 pb0 = __ldg(bp + 0), pb1 = __ldg(bp + 1),
               pb2 = __ldg(bp + 2), pb3 = __ldg(bp + 3);

        for (int ii = 0; ii < FPT; ii++) {
            const int i = i0 + ii;
            float bvals[NB];
            bvals[0]=pb0.x;  bvals[1]=pb0.y;  bvals[2]=pb0.z;  bvals[3]=pb0.w;
            bvals[4]=pb1.x;  bvals[5]=pb1.y;  bvals[6]=pb1.z;  bvals[7]=pb1.w;
            bvals[8]=pb2.x;  bvals[9]=pb2.y;  bvals[10]=pb2.z; bvals[11]=pb2.w;
            bvals[12]=pb3.x; bvals[13]=pb3.y; bvals[14]=pb3.z; bvals[15]=pb3.w;
            if (ii + 1 < FPT) {
                const float4* nx = brow + (i + 1) * 4;
                pb0 = __ldg(nx + 0); pb1 = __ldg(nx + 1);
                pb2 = __ldg(nx + 2); pb3 = __ldg(nx + 3);
            }

            float h[NCOMP], v[NCOMP];
            #pragma unroll
            for (int c = 0; c < NCOMP; c++) { h[c] = 0.0f; v[c] = 0.0f; }

            #pragma unroll
            for (int k = 0; k < NB; k++) {
                const float* wk = &sW[(k * NCONT + i) * WPITCH];
                float4 wh0 = *reinterpret_cast<const float4*>(wk);
                float4 wh1 = *reinterpret_cast<const float4*>(wk + 4);
                float4 wv0 = *reinterpret_cast<const float4*>(wk + 8);
                float4 wv1 = *reinterpret_cast<const float4*>(wk + 12);
                const float bk = bvals[k];
                h[0] = fmaf(bk, wh0.x, h[0]); h[1] = fmaf(bk, wh0.y, h[1]);
                h[2] = fmaf(bk, wh0.z, h[2]); h[3] = fmaf(bk, wh0.w, h[3]);
                h[4] = fmaf(bk, wh1.x, h[4]); h[5] = fmaf(bk, wh1.y, h[5]);
                h[6] = fmaf(bk, wh1.z, h[6]); h[7] = fmaf(bk, wh1.w, h[7]);
                v[0] = fmaf(bk, wv0.x, v[0]); v[1] = fmaf(bk, wv0.y, v[1]);
                v[2] = fmaf(bk, wv0.z, v[2]); v[3] = fmaf(bk, wv0.w, v[3]);
                v[4] = fmaf(bk, wv1.x, v[4]); v[5] = fmaf(bk, wv1.y, v[5]);
                v[6] = fmaf(bk, wv1.z, v[6]); v[7] = fmaf(bk, wv1.w, v[7]);
                ic   = fmaf(bk, wk[16], ic);
            }
            #pragma unroll
            for (int c = 0; c < NCOMP; c++) { hs[c] += sp(h[c]); vs[c] += sp(v[c]); }
        }
    }

    // ---- reduce the 4 feature-groups of this row (lanes r*4+fg, fg=0..3)
    #pragma unroll
    for (int c = 0; c < NCOMP; c++) {
        hs[c] += __shfl_xor_sync(0xffffffffu, hs[c], 1);
        hs[c] += __shfl_xor_sync(0xffffffffu, hs[c], 2);
        vs[c] += __shfl_xor_sync(0xffffffffu, vs[c], 1);
        vs[c] += __shfl_xor_sync(0xffffffffu, vs[c], 2);
    }
    ic += __shfl_xor_sync(0xffffffffu, ic, 1);
    ic += __shfl_xor_sync(0xffffffffu, ic, 2);

    if (fg == 0) {
        // bias column (softplus'ed for H/V, raw for IC)
        #pragma unroll
        for (int c = 0; c < NCOMP; c++) {
            hs[c] += sp(__ldg(bh + c));
            vs[c] += sp(__ldg(bv + c));
        }
        ic += __ldg(bic);

        // epilogue: prefix sums, sep offsets, alternating signs, clamp last t
        float2 o[NCOMP + 1];
        o[0] = make_float2(0.0f, ic);
        float cum = 0.0f, xc = ic;
        #pragma unroll
        for (int c = 0; c < NCOMP; c++) {
            cum += hs[c];
            xc  += (c & 1) ? -vs[c] : vs[c];
            o[c + 1] = make_float2(cum + SEPF * (float)(c + 1), xc);
        }
        o[NCOMP].x = fmaxf(o[NCOMP - 1].x + SEPF, T1F);

        float2* op = reinterpret_cast<float2*>(out + (size_t)row * 2 * (NCOMP + 1));
        #pragma unroll
        for (int j = 0; j < NCOMP + 1; j++) op[j] = o[j];
    }
}

// ---------------------------------------------------------------------------
// Launch wrapper: one kernel. Attribute call is host-side, capture-safe.
// ---------------------------------------------------------------------------
extern "C" void kernel_launch(void* const* d_in, const int* in_sizes, int n_in,
                              void* d_out, int out_size)
{
    const float* B    = (const float*)d_in[0];
    const float* Bcat = (const float*)d_in[1];
    const float* Wh   = (const float*)d_in[2];
    const float* Whc  = (const float*)d_in[3];
    const float* bh   = (const float*)d_in[4];
    const float* Wv   = (const float*)d_in[5];
    const float* Wvc  = (const float*)d_in[6];
    const float* bv   = (const float*)d_in[7];
    const float* Wic  = (const float*)d_in[8];
    const float* Wicc = (const float*)d_in[9];
    const float* bic  = (const float*)d_in[10];
    float* out = (float*)d_out;

    const size_t smem = (size_t)NB * NCONT * WPITCH * sizeof(float); // 71,680 B
    cudaFuncSetAttribute(k_fused, cudaFuncAttributeMaxDynamicSharedMemorySize, (int)smem);

    const int nthreads = BATCH * TPR;
    k_fused<<<nthreads / TPB, TPB, smem>>>(B, Bcat, Wh, bh, Wv, bv, Wic, bic,
                                           Whc, Wvc, Wicc, out);
}